// round 13
// baseline (speedup 1.0000x reference)
#include <cuda_runtime.h>
#include <cstdint>

// TokenBladeBank: FNV-1a 4-gram hash -> gather from 8 blade banks.
// token_window: (8, 8192, 4) int32 OR int64 (detected in-warp)
// bank:         (8, 500000, 16) float32
// out:          (8, 8192, 8, 16) float32  ->  out[pos*128 + blade*16 + d]
//
// R10 structure (best: 12.7us) with gathers moved to cp.async.cg (LDGSTS):
// every previous "MLP=8" build compiled to regs=32, i.e. ptxas waved the
// load batch through ~4 result registers, so true MLP>4 was never tested.
// cp.async has no register dependency and no depth cap: all 8 16B gathers
// per lane are genuinely outstanding (L2->SMEM direct, L1 bypass). SMEM
// staging: buf[warp][pos][lane] 16B slots, LDS.128 4-phase conflict-free.
// Store path unchanged (__stcs, 4KB contiguous per warp).

#define TBB_N_SLOTS    500000u
#define TBB_FNV_OFFSET 2166136261u
#define TBB_FNV_PRIME  16777619u
#define TBB_POS_PER_WARP 8
#define TBB_WARPS_PER_BLK 4

__device__ __forceinline__ unsigned tbb_fnv4(unsigned a, unsigned b,
                                             unsigned c, unsigned d)
{
    unsigned h = TBB_FNV_OFFSET;
    h = (h ^ a) * TBB_FNV_PRIME;
    h = (h ^ b) * TBB_FNV_PRIME;
    h = (h ^ c) * TBB_FNV_PRIME;
    h = (h ^ d) * TBB_FNV_PRIME;
    return h % TBB_N_SLOTS;
}

__global__ void __launch_bounds__(128)
tbb_gather_kernel(const unsigned* __restrict__ tw,
                  const float4*  __restrict__ bank,
                  float4*        __restrict__ out,
                  int n_pos)
{
    // 4 warps x 8 positions x 32 lanes x 16B = 16 KB staging.
    __shared__ float4 buf[TBB_WARPS_PER_BLK][TBB_POS_PER_WARP][32];

    const int t     = blockIdx.x * blockDim.x + threadIdx.x;
    const int warp  = t >> 5;
    const int wblk  = threadIdx.x >> 5;
    const int lane  = t & 31;
    const int pos0  = warp * TBB_POS_PER_WARP;
    if (pos0 >= n_pos) return;

    // In-warp dtype detection: odd 32-bit words of the first 64 token words.
    // int64 LE layout => all zero high-halves (tokens < 50257);
    // int32 layout => random tokens, P(all 32 == 0) ~ 50257^-32 ~ 0.
    const unsigned probe = __ldg(&tw[2 * lane + 1]);
    const unsigned nz    = __ballot_sync(0xffffffffu, probe != 0u);
    const int stride     = (nz == 0u) ? 2 : 1;

    const unsigned blade = (unsigned)lane >> 2;   // 0..7
    const unsigned q     = (unsigned)lane & 3;    // float4 within 16-fp row
    const int      sub   = lane & 7;              // which position I hash

    const uint4* tw4 = (const uint4*)tw;

    // Each lane hashes ONE position (pos0+sub); width-8 shuffles broadcast
    // all 8 addresses to every lane.
    unsigned myaddr;
    if (stride == 1) {
        uint4 tk = __ldg(&tw4[pos0 + sub]);
        myaddr = tbb_fnv4(tk.x, tk.y, tk.z, tk.w);
    } else {
        const size_t p = (size_t)(pos0 + sub) * 2;
        uint4 ta = __ldg(&tw4[p]);
        uint4 tb = __ldg(&tw4[p + 1]);
        myaddr = tbb_fnv4(ta.x, ta.z, tb.x, tb.z);
    }

    // 8 register-free async gathers: ALL genuinely in flight (true MLP=8).
    // Lanes 4b..4b+3 cover one contiguous 64 B row: perfect sector use.
    #pragma unroll
    for (int g = 0; g < TBB_POS_PER_WARP; g++) {
        const unsigned a = __shfl_sync(0xffffffffu, myaddr, g, 8);
        const float4* src =
            &bank[((size_t)blade * TBB_N_SLOTS + (size_t)a) * 4 + q];
        unsigned dst = (unsigned)__cvta_generic_to_shared(&buf[wblk][g][lane]);
        asm volatile("cp.async.cg.shared.global [%0], [%1], 16;"
                     :: "r"(dst), "l"(src) : "memory");
    }
    asm volatile("cp.async.commit_group;" ::: "memory");
    asm volatile("cp.async.wait_group 0;" ::: "memory");
    __syncwarp();

    // Readback (conflict-free LDS.128) + 8 coalesced 512 B streaming stores.
    #pragma unroll
    for (int g = 0; g < TBB_POS_PER_WARP; g++)
        __stcs(&out[(size_t)(pos0 + g) * 32 + lane], buf[wblk][g][lane]);
}

extern "C" void kernel_launch(void* const* d_in, const int* in_sizes, int n_in,
                              void* d_out, int out_size)
{
    const unsigned* tw   = (const unsigned*)d_in[0];
    const float4*   bank = (const float4*)d_in[1];
    float4*         out  = (float4*)d_out;

    const int n_pos = out_size / 128;             // 65536 positions (dtype-proof)

    const int threads = 128;
    const int warps   = (n_pos + TBB_POS_PER_WARP - 1) / TBB_POS_PER_WARP;
    const int blocks  = (warps * 32 + threads - 1) / threads;  // 2048
    tbb_gather_kernel<<<blocks, threads>>>(tw, bank, out, n_pos);
}

// round 14
// speedup vs baseline: 1.0076x; 1.0076x over previous
#include <cuda_runtime.h>
#include <cstdint>

// TokenBladeBank: FNV-1a 4-gram hash -> gather from 8 blade banks.
// token_window: (8, 8192, 4) int32 OR int64 (detected in-warp)
// bank:         (8, 500000, 16) float32
// out:          (8, 8192, 8, 16) float32  ->  out[pos*128 + blade*16 + d]
//
// Pipelined cp.async version: 16 positions/warp in TWO commit-groups of 8.
// Issue A, issue B, wait_group 1 (A complete, B still in flight), store A,
// wait_group 0, store B. Keeps 8KB of reads outstanding per warp and
// overlaps half the store traffic with in-flight reads (the single-phase
// kernels had zero reads in flight during their store phase).
// 64-thread blocks keep grid=2048 (13.8 blocks/SM balance).

#define TBB_N_SLOTS    500000u
#define TBB_FNV_OFFSET 2166136261u
#define TBB_FNV_PRIME  16777619u
#define TBB_POS_PER_WARP 16   // two cp.async groups of 8
#define TBB_WARPS_PER_BLK 2

__device__ __forceinline__ unsigned tbb_fnv4(unsigned a, unsigned b,
                                             unsigned c, unsigned d)
{
    unsigned h = TBB_FNV_OFFSET;
    h = (h ^ a) * TBB_FNV_PRIME;
    h = (h ^ b) * TBB_FNV_PRIME;
    h = (h ^ c) * TBB_FNV_PRIME;
    h = (h ^ d) * TBB_FNV_PRIME;
    return h % TBB_N_SLOTS;
}

__global__ void __launch_bounds__(64)
tbb_gather_kernel(const unsigned* __restrict__ tw,
                  const float4*  __restrict__ bank,
                  float4*        __restrict__ out,
                  int n_pos)
{
    // 2 warps x 16 positions x 32 lanes x 16B = 16 KB staging.
    __shared__ float4 buf[TBB_WARPS_PER_BLK][TBB_POS_PER_WARP][32];

    const int t    = blockIdx.x * blockDim.x + threadIdx.x;
    const int warp = t >> 5;
    const int wblk = threadIdx.x >> 5;
    const int lane = t & 31;
    const int pos0 = warp * TBB_POS_PER_WARP;
    if (pos0 >= n_pos) return;

    // In-warp dtype detection: odd 32-bit words of the first 64 token words.
    // int64 LE layout => all zero high-halves (tokens < 50257);
    // int32 layout => random tokens, P(all 32 == 0) ~ 50257^-32 ~ 0.
    const unsigned probe = __ldg(&tw[2 * lane + 1]);
    const unsigned nz    = __ballot_sync(0xffffffffu, probe != 0u);
    const int stride     = (nz == 0u) ? 2 : 1;

    const unsigned blade = (unsigned)lane >> 2;   // 0..7
    const unsigned q     = (unsigned)lane & 3;    // float4 within 16-fp row
    const int      sub   = lane & 15;             // which position I hash

    const uint4* tw4 = (const uint4*)tw;

    // Each lane hashes ONE of the 16 positions; width-16 shuffles broadcast.
    unsigned myaddr;
    if (stride == 1) {
        uint4 tk = __ldg(&tw4[pos0 + sub]);
        myaddr = tbb_fnv4(tk.x, tk.y, tk.z, tk.w);
    } else {
        const size_t p = (size_t)(pos0 + sub) * 2;
        uint4 ta = __ldg(&tw4[p]);
        uint4 tb = __ldg(&tw4[p + 1]);
        myaddr = tbb_fnv4(ta.x, ta.z, tb.x, tb.z);
    }

    // Group A: positions 0..7 — 8 register-free 16B async gathers.
    #pragma unroll
    for (int g = 0; g < 8; g++) {
        const unsigned a = __shfl_sync(0xffffffffu, myaddr, g, 16);
        const float4* src =
            &bank[((size_t)blade * TBB_N_SLOTS + (size_t)a) * 4 + q];
        unsigned dst = (unsigned)__cvta_generic_to_shared(&buf[wblk][g][lane]);
        asm volatile("cp.async.cg.shared.global [%0], [%1], 16;"
                     :: "r"(dst), "l"(src) : "memory");
    }
    asm volatile("cp.async.commit_group;" ::: "memory");

    // Group B: positions 8..15.
    #pragma unroll
    for (int g = 8; g < 16; g++) {
        const unsigned a = __shfl_sync(0xffffffffu, myaddr, g, 16);
        const float4* src =
            &bank[((size_t)blade * TBB_N_SLOTS + (size_t)a) * 4 + q];
        unsigned dst = (unsigned)__cvta_generic_to_shared(&buf[wblk][g][lane]);
        asm volatile("cp.async.cg.shared.global [%0], [%1], 16;"
                     :: "r"(dst), "l"(src) : "memory");
    }
    asm volatile("cp.async.commit_group;" ::: "memory");

    // Wait for A only: B's 4 KB stays in flight while we store A.
    asm volatile("cp.async.wait_group 1;" ::: "memory");
    __syncwarp();
    #pragma unroll
    for (int g = 0; g < 8; g++)
        __stcs(&out[(size_t)(pos0 + g) * 32 + lane], buf[wblk][g][lane]);

    // Now drain B and store it.
    asm volatile("cp.async.wait_group 0;" ::: "memory");
    __syncwarp();
    #pragma unroll
    for (int g = 8; g < 16; g++)
        __stcs(&out[(size_t)(pos0 + g) * 32 + lane], buf[wblk][g][lane]);
}

extern "C" void kernel_launch(void* const* d_in, const int* in_sizes, int n_in,
                              void* d_out, int out_size)
{
    const unsigned* tw   = (const unsigned*)d_in[0];
    const float4*   bank = (const float4*)d_in[1];
    float4*         out  = (float4*)d_out;

    const int n_pos = out_size / 128;             // 65536 positions (dtype-proof)

    const int threads = 64;
    const int warps   = (n_pos + TBB_POS_PER_WARP - 1) / TBB_POS_PER_WARP;
    const int blocks  = (warps * 32 + threads - 1) / threads;  // 2048
    tbb_gather_kernel<<<blocks, threads>>>(tw, bank, out, n_pos);
}